// round 1
// baseline (speedup 1.0000x reference)
#include <cuda_runtime.h>
#include <cuda_bf16.h>

// ============================================================================
// MatryoshkaQuantizer: argmin over 256 candidate codes of
//   err(q) = (x - s(d8))^2 + 0.5(x - s(d4))^2 + 0.25(x - s(d2))^2,  d = v - z
// collapses (per element) to argmin_q [ B(q) - u*A(q) ],  u = 2x/s + 2(z-128),
// where A,B are compile-time integer tables over the matryoshka levels.
// Lines have strictly decreasing slopes -> argmin is a monotone step function
// of u. The lower envelope (breakpoints + per-segment code) is built entirely
// at compile time via constexpr and baked into a __device__ table.
// ============================================================================

struct Env {
    float bp[256];   // sorted breakpoints in u, padded with +huge
    int   q[256];    // code for segment i (u in (bp[i-1], bp[i]])
};

constexpr int cclip(int v, int hi) { return v > hi ? hi : v; }

constexpr Env make_env() {
    Env e{};
    int A[256] = {};
    int B[256] = {};
    for (int q = 0; q < 256; q++) {
        int d8 = q - 128;
        int v4 = cclip((q >> 4) + ((q >> 3) & 1), 15);
        int d4 = (v4 << 4) - 128;
        int v2 = cclip((q >> 6) + ((q >> 5) & 1), 3);
        int d2 = (v2 << 6) - 128;
        // scaled by 4 to stay integer-exact: A=4*(d8+0.5d4+0.25d2), B likewise
        A[q] = 4 * d8 + 2 * d4 + d2;          // strictly increasing in q
        B[q] = 4 * d8 * d8 + 2 * d4 * d4 + d2 * d2;
    }
    // Lower envelope of lines y_q(u) = B[q] - A[q]*u (slopes strictly decrease
    // with q). Classic monotone-stack hull; exact int64 cross-multiplication.
    int st[256] = {};
    int cnt = 0;
    for (int q = 0; q < 256; q++) {
        while (cnt >= 2) {
            int a = st[cnt - 2], b = st[cnt - 1];
            // inter(a,q) <= inter(a,b)  (denominators A[x]-A[a] > 0)
            long long lhs = (long long)(B[q] - B[a]) * (long long)(A[b] - A[a]);
            long long rhs = (long long)(B[b] - B[a]) * (long long)(A[q] - A[a]);
            if (lhs <= rhs) cnt--; else break;
        }
        st[cnt++] = q;
    }
    for (int i = 0; i < 256; i++) {
        if (i < cnt - 1) {
            // exact small ints (<2^18) -> float division is plenty accurate
            e.bp[i] = (float)(B[st[i + 1]] - B[st[i]]) /
                      (float)(A[st[i + 1]] - A[st[i]]);
        } else {
            e.bp[i] = 3.0e38f;
        }
        e.q[i] = st[i < cnt - 1 ? i : cnt - 1];
    }
    return e;
}

constexpr Env ENV_HOST = make_env();
__device__ const Env g_env = ENV_HOST;

__global__ void __launch_bounds__(256)
matryoshka_kernel(const float* __restrict__ x,
                  const float* __restrict__ scale,
                  const float* __restrict__ zero,
                  float* __restrict__ out,
                  int n, int cols) {
    __shared__ float s_bp[256];
    __shared__ int   s_q[256];
    int t = threadIdx.x;
    s_bp[t] = g_env.bp[t];
    s_q[t]  = g_env.q[t];
    __syncthreads();

    int idx = blockIdx.x * 256 + t;
    if (idx >= n) return;

    int   r  = idx / cols;
    float xv = x[idx];
    float s  = __ldg(scale + r);
    float z  = __ldg(zero + r);

    // u = 2*x/s + 2*(z - 128): the envelope coordinate
    float u = 2.0f * (xv / s) + 2.0f * (z - 128.0f);

    // branchless lower_bound over 256 padded breakpoints:
    // lo = #{breakpoints < u}; exact ties pick the lower code (matches
    // jnp.argmin first-index tie rule).
    int lo = 0;
    #pragma unroll
    for (int stp = 128; stp; stp >>= 1)
        lo += (s_bp[lo + stp - 1] < u) ? stp : 0;
    int q = s_q[lo];

    // reconstruct slice levels for the chosen code
    int v4 = min((q >> 4) + ((q >> 3) & 1), 15);
    int v2 = min((q >> 6) + ((q >> 5) & 1), 3);
    float s8 = (float)q;
    float s4 = (float)(v4 << 4);
    float s2 = (float)(v2 << 6);

    // loss_sel = sum of raw residuals, replicating reference rounding order
    // (sub, mul, sub per slice; accumulate 8 then 4 then 2; no FMA fusion)
    float l8 = __fsub_rn(xv, __fmul_rn(s, __fsub_rn(s8, z)));
    float l4 = __fsub_rn(xv, __fmul_rn(s, __fsub_rn(s4, z)));
    float l2 = __fsub_rn(xv, __fmul_rn(s, __fsub_rn(s2, z)));
    float loss = __fadd_rn(__fadd_rn(l8, l4), l2);

    out[idx]     = (float)q;   // qweight (uint8 in ref, promoted to f32)
    out[n + idx] = loss;       // selected loss
}

extern "C" void kernel_launch(void* const* d_in, const int* in_sizes, int n_in,
                              void* d_out, int out_size) {
    const float* x     = (const float*)d_in[0];
    const float* scale = (const float*)d_in[1];
    const float* zero  = (const float*)d_in[2];
    // d_in[3] = maxq (255) — tables assume 255, matching the dataset.

    int n    = in_sizes[0];                  // rows*cols = 262144
    int rows = (n_in > 1) ? in_sizes[1] : 1; // 1024
    int cols = n / (rows > 0 ? rows : 1);    // 256

    int blocks = (n + 255) / 256;
    matryoshka_kernel<<<blocks, 256>>>(x, scale, zero, (float*)d_out, n, cols);
}